// round 5
// baseline (speedup 1.0000x reference)
#include <cuda_runtime.h>
#include <math.h>
#include <stdint.h>

// EdgeEmbedding: pure elementwise map over edges (R0 analysis: the pair
// segment-mean and SH parity cancel bit-exactly):
//   edge_length    = ||edge_vec||
//   edge_embedding = bessel(||edge_vec||) * cutoff(||edge_vec||)
//   edge_attr      = SH_l<=2(edge_vec / ||edge_vec||)
// Output layout: [len (E) | emb (E,8) | attr (E,9)].
//
// R4: persistent grid (148 SM x 8 blocks) with grid-stride tile loop and
// double-buffered attr staging -> no wave transitions, one sync per tile,
// next tile's loads overlap previous tile's store drain. (R3 showed we are
// at ~82% of HBM spec; the remaining gap is wave ramp/drain dead time.)

#define EPB 256                 // edges per tile == threads per block
#define PERSIST_BLOCKS 1184     // 148 SMs x 8 blocks/SM

__device__ __forceinline__ void edge_math(float x, float y, float z,
                                          float& len, float* emb8, float* attr9)
{
    const float S3   = 1.7320508075688772f;   // sqrt(3)
    const float S5   = 2.2360679774997896f;   // sqrt(5)
    const float S15  = 3.8729833462074170f;   // sqrt(15)
    const float PI_F = 3.14159265358979323846f;
    const float SQRT_2_OVER_RC = 0.6324555320336759f; // sqrt(2/5)
    const float INV_RC = 0.2f;

    float r2  = fmaf(x, x, fmaf(y, y, z * z));
    float inv = rsqrtf(fmaxf(r2, 1e-24f));    // 1/r  (single MUFU.RSQ)
    float r   = r2 * inv;                     // r = r2 / sqrt(r2)
    len = r;

    // spherical harmonics l<=2 on u = vec/r
    float ux = x * inv, uy = y * inv, uz = z * inv;
    attr9[0] = 1.0f;
    attr9[1] = S3 * ux;
    attr9[2] = S3 * uy;
    attr9[3] = S3 * uz;
    attr9[4] = S15 * ux * uy;
    attr9[5] = S15 * uy * uz;
    attr9[6] = 0.5f * S5 * fmaf(3.0f * uz, uz, -1.0f);
    attr9[7] = S15 * ux * uz;
    attr9[8] = 0.5f * S15 * (ux * ux - uy * uy);

    // polynomial cutoff (p=6): 1 - 28 q^6 + 48 q^7 - 21 q^8
    float q  = r * INV_RC;
    float q2 = q * q;
    float q3 = q2 * q;
    float q6 = q3 * q3;
    float env = fmaf(q6, fmaf(q, fmaf(-21.0f, q, 48.0f), -28.0f), 1.0f);
    env = (q < 1.0f) ? env : 0.0f;

    // bessel: sqrt(2/RC) * sin(k*pi*q)/r_safe * env, k=1..8
    // Chebyshev recurrence: sin((k+1)t) = 2cos(t)sin(kt) - sin((k-1)t)
    float st, ct;
    __sincosf(PI_F * q, &st, &ct);            // MUFU sin/cos, |x| <= ~pi
    float pre  = SQRT_2_OVER_RC * inv * env;
    float twoc = 2.0f * ct;
    float sk_m1 = 0.0f, sk = st;
#pragma unroll
    for (int k = 0; k < 8; k++) {
        emb8[k] = pre * sk;
        float nxt = fmaf(twoc, sk, -sk_m1);
        sk_m1 = sk;
        sk = nxt;
    }
}

__global__ __launch_bounds__(EPB)
void edge_embed_r4(const float* __restrict__ vec,
                   float* __restrict__ out,
                   int E, int ntiles, int vec_ok)
{
    // double-buffered linear attr staging: edge i at words [i*9, i*9+9)
    __shared__ float attr_s[2][EPB * 9];

    const int tid = threadIdx.x;
    int buf = 0;

    for (int tile = blockIdx.x; tile < ntiles; tile += gridDim.x, buf ^= 1) {
        const long long base = (long long)tile * EPB;
        const int nedge = (int)(((base + EPB) <= (long long)E)
                                    ? (long long)EPB : ((long long)E - base));

        if (tid < nedge) {
            long long e = base + tid;
            float x = __ldcs(&vec[3 * e + 0]);
            float y = __ldcs(&vec[3 * e + 1]);
            float z = __ldcs(&vec[3 * e + 2]);
            float len, emb[8], a9[9];
            edge_math(x, y, z, len, emb, a9);

            // len: naturally coalesced
            __stcs(&out[e], len);

            // emb: direct from registers (each float4 is one thread's data)
            float* oe = out + (long long)E + e * 8;
            if (vec_ok) {
                float4* pe = reinterpret_cast<float4*>(oe);
                __stcs(&pe[0], make_float4(emb[0], emb[1], emb[2], emb[3]));
                __stcs(&pe[1], make_float4(emb[4], emb[5], emb[6], emb[7]));
            } else {
#pragma unroll
                for (int k = 0; k < 8; k++) oe[k] = emb[k];
            }

            // attr: stage linearly (stride-9 STS is bank-conflict-free)
#pragma unroll
            for (int k = 0; k < 9; k++) attr_s[buf][tid * 9 + k] = a9[k];
        }
        __syncthreads();
        // NOTE: single sync per tile is safe with double buffering:
        // STS(tile+2 -> buf) is ordered after sync(tile+1), which is after
        // every thread's writeout(tile, buf).

        // attr writeout: nedge*9 contiguous floats
        float* oa = out + 9LL * E + base * 9;
        if (nedge == EPB && vec_ok) {
            const float4* s4 = reinterpret_cast<const float4*>(attr_s[buf]);
            float4* g4 = reinterpret_cast<float4*>(oa);
            __stcs(&g4[tid],       s4[tid]);
            __stcs(&g4[tid + EPB], s4[tid + EPB]);
            if (tid < (EPB * 9) / 4 - 2 * EPB)           // 64 remaining
                __stcs(&g4[tid + 2 * EPB], s4[tid + 2 * EPB]);
        } else {
            const int ntot = nedge * 9;
            for (int s = tid; s < ntot; s += EPB)
                oa[s] = attr_s[buf][s];
        }
    }
}

extern "C" void kernel_launch(void* const* d_in, const int* in_sizes, int n_in,
                              void* d_out, int out_size)
{
    const float* edge_vec = (const float*)d_in[0];
    int E = in_sizes[0] / 3;
    float* out = (float*)d_out;

    // float4 paths require 16B alignment of out+E (offset 8e) and the attr
    // tile bases (9E + 2304*tile)  ->  E % 4 == 0.
    int vec_ok = ((E & 3) == 0) ? 1 : 0;

    int ntiles = (E + EPB - 1) / EPB;
    int blocks = ntiles < PERSIST_BLOCKS ? ntiles : PERSIST_BLOCKS;
    edge_embed_r4<<<blocks, EPB>>>(edge_vec, out, E, ntiles, vec_ok);
}

// round 6
// speedup vs baseline: 1.1228x; 1.1228x over previous
#include <cuda_runtime.h>
#include <math.h>
#include <stdint.h>

// EdgeEmbedding: pure elementwise map over edges (R0 analysis: the pair
// segment-mean and SH parity cancel bit-exactly):
//   edge_length    = ||edge_vec||
//   edge_embedding = bessel(||edge_vec||) * cutoff(||edge_vec||)
//   edge_attr      = SH_l<=2(edge_vec / ||edge_vec||)
// Output layout: [len (E) | emb (E,8) | attr (E,9)].
//
// R5 = revert of the R4 persistent-grid regression (barrier-coupled tile
// loop cost more than wave transitions) back to the R3 structure, plus
// coalesced float4 input staging through smem (stride-3 scalar LDGs were
// 3x wavefront-amplified; stride-3 LDS is bank-conflict-free since
// gcd(3,32)=1).

#define EPB 256   // edges per block == threads per block

__device__ __forceinline__ void edge_math(float x, float y, float z,
                                          float& len, float* emb8, float* attr9)
{
    const float S3   = 1.7320508075688772f;   // sqrt(3)
    const float S5   = 2.2360679774997896f;   // sqrt(5)
    const float S15  = 3.8729833462074170f;   // sqrt(15)
    const float PI_F = 3.14159265358979323846f;
    const float SQRT_2_OVER_RC = 0.6324555320336759f; // sqrt(2/5)
    const float INV_RC = 0.2f;

    float r2  = fmaf(x, x, fmaf(y, y, z * z));
    float inv = rsqrtf(fmaxf(r2, 1e-24f));    // 1/r  (single MUFU.RSQ)
    float r   = r2 * inv;                     // r = r2 / sqrt(r2)
    len = r;

    // spherical harmonics l<=2 on u = vec/r
    float ux = x * inv, uy = y * inv, uz = z * inv;
    attr9[0] = 1.0f;
    attr9[1] = S3 * ux;
    attr9[2] = S3 * uy;
    attr9[3] = S3 * uz;
    attr9[4] = S15 * ux * uy;
    attr9[5] = S15 * uy * uz;
    attr9[6] = 0.5f * S5 * fmaf(3.0f * uz, uz, -1.0f);
    attr9[7] = S15 * ux * uz;
    attr9[8] = 0.5f * S15 * (ux * ux - uy * uy);

    // polynomial cutoff (p=6): 1 - 28 q^6 + 48 q^7 - 21 q^8
    float q  = r * INV_RC;
    float q2 = q * q;
    float q3 = q2 * q;
    float q6 = q3 * q3;
    float env = fmaf(q6, fmaf(q, fmaf(-21.0f, q, 48.0f), -28.0f), 1.0f);
    env = (q < 1.0f) ? env : 0.0f;

    // bessel: sqrt(2/RC) * sin(k*pi*q)/r_safe * env, k=1..8
    // Chebyshev recurrence: sin((k+1)t) = 2cos(t)sin(kt) - sin((k-1)t)
    float st, ct;
    __sincosf(PI_F * q, &st, &ct);            // MUFU sin/cos, |x| <= ~pi
    float pre  = SQRT_2_OVER_RC * inv * env;
    float twoc = 2.0f * ct;
    float sk_m1 = 0.0f, sk = st;
#pragma unroll
    for (int k = 0; k < 8; k++) {
        emb8[k] = pre * sk;
        float nxt = fmaf(twoc, sk, -sk_m1);
        sk_m1 = sk;
        sk = nxt;
    }
}

__global__ __launch_bounds__(EPB)
void edge_embed_r5(const float* __restrict__ vec,
                   float* __restrict__ out,
                   int E, int vec_ok)
{
    __shared__ float in_s[EPB * 3];        // 3 KB input staging
    __shared__ float attr_s[EPB * 9];      // 9 KB attr staging (linear)

    const int tid = threadIdx.x;
    const long long base = (long long)blockIdx.x * EPB;
    const int nedge = (int)(((base + EPB) <= (long long)E)
                                ? (long long)EPB : ((long long)E - base));

    // ---- coalesced input load: EPB*3 floats ----
    if (nedge == EPB && vec_ok) {
        // 192 float4 loads (threads 0..191), fully coalesced
        const float4* v4 = reinterpret_cast<const float4*>(vec + base * 3);
        if (tid < (EPB * 3) / 4)
            reinterpret_cast<float4*>(in_s)[tid] = __ldcs(&v4[tid]);
    } else {
        const int ntot = nedge * 3;
        for (int s = tid; s < ntot; s += EPB)
            in_s[s] = vec[base * 3 + s];
    }
    __syncthreads();

    if (tid < nedge) {
        long long e = base + tid;
        float x = in_s[3 * tid + 0];       // stride-3 LDS: conflict-free
        float y = in_s[3 * tid + 1];
        float z = in_s[3 * tid + 2];
        float len, emb[8], a9[9];
        edge_math(x, y, z, len, emb, a9);

        // len: naturally coalesced
        __stcs(&out[e], len);

        // emb: direct from registers (each float4 is one thread's data)
        float* oe = out + (long long)E + e * 8;
        if (vec_ok) {
            float4* pe = reinterpret_cast<float4*>(oe);
            __stcs(&pe[0], make_float4(emb[0], emb[1], emb[2], emb[3]));
            __stcs(&pe[1], make_float4(emb[4], emb[5], emb[6], emb[7]));
        } else {
#pragma unroll
            for (int k = 0; k < 8; k++) oe[k] = emb[k];
        }

        // attr: stage linearly (stride-9 STS is bank-conflict-free)
#pragma unroll
        for (int k = 0; k < 9; k++) attr_s[tid * 9 + k] = a9[k];
    }
    __syncthreads();

    // attr writeout: nedge*9 contiguous floats
    float* oa = out + 9LL * E + base * 9;
    if (nedge == EPB && vec_ok) {
        const float4* s4 = reinterpret_cast<const float4*>(attr_s);
        float4* g4 = reinterpret_cast<float4*>(oa);
        __stcs(&g4[tid],       s4[tid]);
        __stcs(&g4[tid + EPB], s4[tid + EPB]);
        if (tid < (EPB * 9) / 4 - 2 * EPB)               // 64 remaining
            __stcs(&g4[tid + 2 * EPB], s4[tid + 2 * EPB]);
    } else {
        const int ntot = nedge * 9;
        for (int s = tid; s < ntot; s += EPB)
            oa[s] = attr_s[s];
    }
}

extern "C" void kernel_launch(void* const* d_in, const int* in_sizes, int n_in,
                              void* d_out, int out_size)
{
    const float* edge_vec = (const float*)d_in[0];
    int E = in_sizes[0] / 3;
    float* out = (float*)d_out;

    // float4 paths require 16B alignment of out+E (offset 8e), the attr
    // tile bases (9E + 2304*bid), and the input tile bases (3*256*bid ok)
    // -> E % 4 == 0.
    int vec_ok = ((E & 3) == 0) ? 1 : 0;

    int blocks = (E + EPB - 1) / EPB;
    edge_embed_r5<<<blocks, EPB>>>(edge_vec, out, E, vec_ok);
}

// round 7
// speedup vs baseline: 1.1412x; 1.0163x over previous
#include <cuda_runtime.h>
#include <math.h>
#include <stdint.h>

// EdgeEmbedding: pure elementwise map over edges (R0 analysis: the pair
// segment-mean and SH parity cancel bit-exactly):
//   edge_length    = ||edge_vec||
//   edge_embedding = bessel(||edge_vec||) * cutoff(||edge_vec||)
//   edge_attr      = SH_l<=2(edge_vec / ||edge_vec||)
// Output layout: [len (E) | emb (E,8) | attr (E,9)].
//
// R6: R3 structure but with WARP-PRIVATE attr staging (1152B smem slice per
// warp, __syncwarp only). R4 (persistent grid) and R5 (extra input-staging
// barrier) both regressed: on this kernel block-wide barriers cost more
// than the wavefronts they save. This removes ALL block-level sync so
// warps stream independently.

#define EPB 256   // edges per block == threads per block (8 warps)

__device__ __forceinline__ void edge_math(float x, float y, float z,
                                          float& len, float* emb8, float* attr9)
{
    const float S3   = 1.7320508075688772f;   // sqrt(3)
    const float S5   = 2.2360679774997896f;   // sqrt(5)
    const float S15  = 3.8729833462074170f;   // sqrt(15)
    const float PI_F = 3.14159265358979323846f;
    const float SQRT_2_OVER_RC = 0.6324555320336759f; // sqrt(2/5)
    const float INV_RC = 0.2f;

    float r2  = fmaf(x, x, fmaf(y, y, z * z));
    float inv = rsqrtf(fmaxf(r2, 1e-24f));    // 1/r  (single MUFU.RSQ)
    float r   = r2 * inv;                     // r = r2 / sqrt(r2)
    len = r;

    // spherical harmonics l<=2 on u = vec/r
    float ux = x * inv, uy = y * inv, uz = z * inv;
    attr9[0] = 1.0f;
    attr9[1] = S3 * ux;
    attr9[2] = S3 * uy;
    attr9[3] = S3 * uz;
    attr9[4] = S15 * ux * uy;
    attr9[5] = S15 * uy * uz;
    attr9[6] = 0.5f * S5 * fmaf(3.0f * uz, uz, -1.0f);
    attr9[7] = S15 * ux * uz;
    attr9[8] = 0.5f * S15 * (ux * ux - uy * uy);

    // polynomial cutoff (p=6): 1 - 28 q^6 + 48 q^7 - 21 q^8
    float q  = r * INV_RC;
    float q2 = q * q;
    float q3 = q2 * q;
    float q6 = q3 * q3;
    float env = fmaf(q6, fmaf(q, fmaf(-21.0f, q, 48.0f), -28.0f), 1.0f);
    env = (q < 1.0f) ? env : 0.0f;

    // bessel: sqrt(2/RC) * sin(k*pi*q)/r_safe * env, k=1..8
    // Chebyshev recurrence: sin((k+1)t) = 2cos(t)sin(kt) - sin((k-1)t)
    float st, ct;
    __sincosf(PI_F * q, &st, &ct);            // MUFU sin/cos, |x| <= ~pi
    float pre  = SQRT_2_OVER_RC * inv * env;
    float twoc = 2.0f * ct;
    float sk_m1 = 0.0f, sk = st;
#pragma unroll
    for (int k = 0; k < 8; k++) {
        emb8[k] = pre * sk;
        float nxt = fmaf(twoc, sk, -sk_m1);
        sk_m1 = sk;
        sk = nxt;
    }
}

__global__ __launch_bounds__(EPB)
void edge_embed_r6(const float* __restrict__ vec,
                   float* __restrict__ out,
                   int E, int vec_ok)
{
    // per-warp slices: warp w owns words [w*288, (w+1)*288)
    __shared__ float attr_s[EPB * 9];

    const int tid  = threadIdx.x;
    const int lane = tid & 31;
    const int wid  = tid >> 5;
    const long long base = (long long)blockIdx.x * EPB;
    const int nedge = (int)(((base + EPB) <= (long long)E)
                                ? (long long)EPB : ((long long)E - base));

    // this warp has all 32 edges valid?
    const bool warp_full = ((wid * 32 + 32) <= nedge) && vec_ok;
    float* warp_s = attr_s + wid * 288;

    if (tid < nedge) {
        long long e = base + tid;
        float x = __ldcs(&vec[3 * e + 0]);
        float y = __ldcs(&vec[3 * e + 1]);
        float z = __ldcs(&vec[3 * e + 2]);
        float len, emb[8], a9[9];
        edge_math(x, y, z, len, emb, a9);

        // len: naturally coalesced
        __stcs(&out[e], len);

        // emb: direct from registers (each float4 is one thread's data)
        float* oe = out + (long long)E + e * 8;
        if (vec_ok) {
            float4* pe = reinterpret_cast<float4*>(oe);
            __stcs(&pe[0], make_float4(emb[0], emb[1], emb[2], emb[3]));
            __stcs(&pe[1], make_float4(emb[4], emb[5], emb[6], emb[7]));
        } else {
#pragma unroll
            for (int k = 0; k < 8; k++) oe[k] = emb[k];
        }

        if (warp_full) {
            // stage into this warp's private slice
            // (stride-9 STS, 9 ⊥ 32 -> bank-conflict-free)
#pragma unroll
            for (int k = 0; k < 9; k++) warp_s[lane * 9 + k] = a9[k];
        } else {
            // tail / unaligned: direct scalar stores (rare)
            float* oa = out + 9LL * E + e * 9;
#pragma unroll
            for (int k = 0; k < 9; k++) oa[k] = a9[k];
        }
    }

    if (warp_full) {
        __syncwarp();
        // warp's 288 contiguous floats = 72 float4s; base 16B-aligned:
        // 9E (E%4==0) + 2304*bid + 288*wid all multiples of 4 floats.
        const float4* s4 = reinterpret_cast<const float4*>(warp_s);
        float4* g4 = reinterpret_cast<float4*>(out + 9LL * E
                                               + (base + wid * 32) * 9);
        __stcs(&g4[lane],      s4[lane]);
        __stcs(&g4[lane + 32], s4[lane + 32]);
        if (lane < 8)
            __stcs(&g4[lane + 64], s4[lane + 64]);
    }
}

extern "C" void kernel_launch(void* const* d_in, const int* in_sizes, int n_in,
                              void* d_out, int out_size)
{
    const float* edge_vec = (const float*)d_in[0];
    int E = in_sizes[0] / 3;
    float* out = (float*)d_out;

    // float4 paths require 16B alignment of out+E (offset 8e) and the attr
    // warp bases (9E + 2304*bid + 288*wid)  ->  E % 4 == 0.
    int vec_ok = ((E & 3) == 0) ? 1 : 0;

    int blocks = (E + EPB - 1) / EPB;
    edge_embed_r6<<<blocks, EPB>>>(edge_vec, out, E, vec_ok);
}

// round 8
// speedup vs baseline: 1.1420x; 1.0007x over previous
#include <cuda_runtime.h>
#include <math.h>
#include <stdint.h>

// EdgeEmbedding: pure elementwise map over edges (R0 analysis: the pair
// segment-mean and SH parity cancel bit-exactly):
//   edge_length    = ||edge_vec||
//   edge_embedding = bessel(||edge_vec||) * cutoff(||edge_vec||)
//   edge_attr      = SH_l<=2(edge_vec / ||edge_vec||)
// Output layout: [len (E) | emb (E,8) | attr (E,9)].
//
// R7 = R6 (warp-private staging, NO block-level sync) + warp-cooperative
// float4 input staging: lanes 0..23 issue 24 coalesced LDG.128 for the
// warp's 384B of input (3 wavefronts instead of 9 for stride-12 scalar
// loads), __syncwarp, then conflict-free stride-3 LDS (gcd(3,32)=1).

#define EPB 256   // edges per block == threads per block (8 warps)

__device__ __forceinline__ void edge_math(float x, float y, float z,
                                          float& len, float* emb8, float* attr9)
{
    const float S3   = 1.7320508075688772f;   // sqrt(3)
    const float S5   = 2.2360679774997896f;   // sqrt(5)
    const float S15  = 3.8729833462074170f;   // sqrt(15)
    const float PI_F = 3.14159265358979323846f;
    const float SQRT_2_OVER_RC = 0.6324555320336759f; // sqrt(2/5)
    const float INV_RC = 0.2f;

    float r2  = fmaf(x, x, fmaf(y, y, z * z));
    float inv = rsqrtf(fmaxf(r2, 1e-24f));    // 1/r  (single MUFU.RSQ)
    float r   = r2 * inv;                     // r = r2 / sqrt(r2)
    len = r;

    // spherical harmonics l<=2 on u = vec/r
    float ux = x * inv, uy = y * inv, uz = z * inv;
    attr9[0] = 1.0f;
    attr9[1] = S3 * ux;
    attr9[2] = S3 * uy;
    attr9[3] = S3 * uz;
    attr9[4] = S15 * ux * uy;
    attr9[5] = S15 * uy * uz;
    attr9[6] = 0.5f * S5 * fmaf(3.0f * uz, uz, -1.0f);
    attr9[7] = S15 * ux * uz;
    attr9[8] = 0.5f * S15 * (ux * ux - uy * uy);

    // polynomial cutoff (p=6): 1 - 28 q^6 + 48 q^7 - 21 q^8
    float q  = r * INV_RC;
    float q2 = q * q;
    float q3 = q2 * q;
    float q6 = q3 * q3;
    float env = fmaf(q6, fmaf(q, fmaf(-21.0f, q, 48.0f), -28.0f), 1.0f);
    env = (q < 1.0f) ? env : 0.0f;

    // bessel: sqrt(2/RC) * sin(k*pi*q)/r_safe * env, k=1..8
    // Chebyshev recurrence: sin((k+1)t) = 2cos(t)sin(kt) - sin((k-1)t)
    float st, ct;
    __sincosf(PI_F * q, &st, &ct);            // MUFU sin/cos, |x| <= ~pi
    float pre  = SQRT_2_OVER_RC * inv * env;
    float twoc = 2.0f * ct;
    float sk_m1 = 0.0f, sk = st;
#pragma unroll
    for (int k = 0; k < 8; k++) {
        emb8[k] = pre * sk;
        float nxt = fmaf(twoc, sk, -sk_m1);
        sk_m1 = sk;
        sk = nxt;
    }
}

__global__ __launch_bounds__(EPB)
void edge_embed_r7(const float* __restrict__ vec,
                   float* __restrict__ out,
                   int E, int vec_ok)
{
    // per-warp slices
    __shared__ float in_s[8][96];          // 384B input per warp
    __shared__ float attr_s[8][288];       // 1152B attr per warp

    const int tid  = threadIdx.x;
    const int lane = tid & 31;
    const int wid  = tid >> 5;
    const long long base = (long long)blockIdx.x * EPB;
    const int nedge = (int)(((base + EPB) <= (long long)E)
                                ? (long long)EPB : ((long long)E - base));

    // this warp has all 32 edges valid & alignment ok?
    const bool warp_full = ((wid * 32 + 32) <= nedge) && vec_ok;
    const long long e = base + tid;

    float x, y, z;
    if (warp_full) {
        // warp-cooperative input: 24 lanes load the warp's 96 floats as
        // float4 (fully coalesced), stage, then stride-3 LDS.
        const float4* v4 = reinterpret_cast<const float4*>(vec + (base + wid * 32) * 3);
        if (lane < 24)
            reinterpret_cast<float4*>(in_s[wid])[lane] = __ldcs(&v4[lane]);
        __syncwarp();
        x = in_s[wid][3 * lane + 0];
        y = in_s[wid][3 * lane + 1];
        z = in_s[wid][3 * lane + 2];
    } else if (tid < nedge) {
        x = vec[3 * e + 0];
        y = vec[3 * e + 1];
        z = vec[3 * e + 2];
    }

    if (tid < nedge) {
        float len, emb[8], a9[9];
        edge_math(x, y, z, len, emb, a9);

        // len: naturally coalesced
        __stcs(&out[e], len);

        // emb: direct from registers (each float4 is one thread's data)
        float* oe = out + (long long)E + e * 8;
        if (vec_ok) {
            float4* pe = reinterpret_cast<float4*>(oe);
            __stcs(&pe[0], make_float4(emb[0], emb[1], emb[2], emb[3]));
            __stcs(&pe[1], make_float4(emb[4], emb[5], emb[6], emb[7]));
        } else {
#pragma unroll
            for (int k = 0; k < 8; k++) oe[k] = emb[k];
        }

        if (warp_full) {
            // stage attr into this warp's slice
            // (stride-9 STS, 9 ⊥ 32 -> bank-conflict-free)
#pragma unroll
            for (int k = 0; k < 9; k++) attr_s[wid][lane * 9 + k] = a9[k];
        } else {
            // tail / unaligned: direct scalar stores (rare)
            float* oa = out + 9LL * E + e * 9;
#pragma unroll
            for (int k = 0; k < 9; k++) oa[k] = a9[k];
        }
    }

    if (warp_full) {
        __syncwarp();
        // warp's 288 contiguous floats = 72 float4s; bases 16B-aligned:
        // 9E (E%4==0), 2304*bid, 288*wid are all multiples of 4 floats.
        const float4* s4 = reinterpret_cast<const float4*>(attr_s[wid]);
        float4* g4 = reinterpret_cast<float4*>(out + 9LL * E
                                               + (base + wid * 32) * 9);
        __stcs(&g4[lane],      s4[lane]);
        __stcs(&g4[lane + 32], s4[lane + 32]);
        if (lane < 8)
            __stcs(&g4[lane + 64], s4[lane + 64]);
    }
}

extern "C" void kernel_launch(void* const* d_in, const int* in_sizes, int n_in,
                              void* d_out, int out_size)
{
    const float* edge_vec = (const float*)d_in[0];
    int E = in_sizes[0] / 3;
    float* out = (float*)d_out;

    // vectorized paths require 16B alignment of out+E (offset 8e), the attr
    // warp bases (9E + 2304*bid + 288*wid), and the input warp bases
    // (12B * 32-edge groups -> 384B multiples)  ->  E % 4 == 0.
    int vec_ok = ((E & 3) == 0) ? 1 : 0;

    int blocks = (E + EPB - 1) / EPB;
    edge_embed_r7<<<blocks, EPB>>>(edge_vec, out, E, vec_ok);
}